// round 4
// baseline (speedup 1.0000x reference)
#include <cuda_runtime.h>
#include <math.h>

#define Bn 8
#define Tn 96
#define Sn 192
#define Dn 512
#define BT (Bn*Tn)   // 768
#define BS (Bn*Sn)   // 1536

// Scratch
__device__ float g_wq  [BT * Dn];
__device__ float g_uh  [BS * Dn];
__device__ float g_wm  [BS * Dn];
__device__ float g_base[BT * Dn];
__device__ float g_p   [BT * Sn];

__device__ __forceinline__ float tanh_fast(float x) {
    float y;
    asm("tanh.approx.f32 %0, %1;" : "=f"(y) : "f"(x));
    return y;
}

typedef unsigned long long u64;

__device__ __forceinline__ void ffma2(u64& d, u64 a, u64 b) {
    asm("fma.rn.f32x2 %0, %1, %2, %0;" : "+l"(d) : "l"(a), "l"(b));
}
__device__ __forceinline__ u64 splat2(float a) {
    u64 r;
    asm("mov.b64 %0, {%1, %1};" : "=l"(r) : "f"(a));
    return r;
}
__device__ __forceinline__ void unpack2(u64 p, float& lo, float& hi) {
    asm("mov.b64 {%0, %1}, %2;" : "=f"(lo), "=f"(hi) : "l"(p));
}

// ----------------------------------------------------------------------------
// Stage 1: four independent NT GEMMs, 128x128 tile, 256 thr, 8x8 microtile,
// packed f32x2 FMA, double-buffered smem. K=512 for all segments.
//   y<6  : wq   = inputs @ Wq^T
//   y<18 : uh   = mems @ Wc^T + bc
//   y<30 : Wm   = mems @ Woc^T          (Wout cols 0..511, ld 1024)
//   else : base = inputs @ Woi^T + bout (Wout cols 512..1023)
// Grid (4, 36) = 144 CTAs = one wave.
// ----------------------------------------------------------------------------
__global__ void __launch_bounds__(256, 1) stage1_gemms(
    const float* __restrict__ inputs, const float* __restrict__ mems,
    const float* __restrict__ Wq, const float* __restrict__ Wc,
    const float* __restrict__ bc, const float* __restrict__ Wout,
    const float* __restrict__ bout,
    float* __restrict__ wq_o, float* __restrict__ uh_o,
    float* __restrict__ wm_o, float* __restrict__ base_o)
{
    const int y = blockIdx.y;
    const float* A; const float* W; int ldw; const float* bias; float* C; int row0;
    if (y < 6)       { A = inputs; W = Wq;         ldw = 512;  bias = nullptr; C = wq_o;   row0 = y * 128; }
    else if (y < 18) { A = mems;   W = Wc;         ldw = 512;  bias = bc;      C = uh_o;   row0 = (y-6)*128; }
    else if (y < 30) { A = mems;   W = Wout;       ldw = 1024; bias = nullptr; C = wm_o;   row0 = (y-18)*128; }
    else             { A = inputs; W = Wout + 512; ldw = 1024; bias = bout;    C = base_o; row0 = (y-30)*128; }

    __shared__ __align__(16) float As[2][16][132];
    __shared__ __align__(16) float Bs[2][16][132];

    const int tid  = threadIdx.x;
    const int col0 = blockIdx.x * 128;
    const int lrow = tid >> 1;            // 0..127
    const int lk8  = (tid & 1) << 3;      // 0 or 8

    const float* aptr = A + (size_t)(row0 + lrow) * Dn  + lk8;
    const float* wptr = W + (size_t)(col0 + lrow) * ldw + lk8;

    const int tm = tid >> 4;              // 0..15 -> rows tm*8..+7
    const int tn = tid & 15;              // cols tn*8..+7

    u64 acc[8][4];
    #pragma unroll
    for (int i = 0; i < 8; i++)
        #pragma unroll
        for (int j = 0; j < 4; j++) acc[i][j] = 0ull;

    float4 av0 = *(const float4*)(aptr);
    float4 av1 = *(const float4*)(aptr + 4);
    float4 wv0 = *(const float4*)(wptr);
    float4 wv1 = *(const float4*)(wptr + 4);

    {
        float aa[8] = {av0.x,av0.y,av0.z,av0.w,av1.x,av1.y,av1.z,av1.w};
        float ww[8] = {wv0.x,wv0.y,wv0.z,wv0.w,wv1.x,wv1.y,wv1.z,wv1.w};
        #pragma unroll
        for (int i = 0; i < 8; i++) {
            As[0][lk8 + i][lrow] = aa[i];
            Bs[0][lk8 + i][lrow] = ww[i];
        }
    }
    __syncthreads();

    #pragma unroll 1
    for (int c = 0; c < 32; c++) {
        const int cur = c & 1;
        if (c < 31) {
            av0 = *(const float4*)(aptr + (c + 1) * 16);
            av1 = *(const float4*)(aptr + (c + 1) * 16 + 4);
            wv0 = *(const float4*)(wptr + (c + 1) * 16);
            wv1 = *(const float4*)(wptr + (c + 1) * 16 + 4);
        }
        #pragma unroll
        for (int k = 0; k < 16; k++) {
            ulonglong2 b0 = *(const ulonglong2*)&Bs[cur][k][tn * 8];
            ulonglong2 b1 = *(const ulonglong2*)&Bs[cur][k][tn * 8 + 4];
            float4 af0 = *(const float4*)&As[cur][k][tm * 8];
            float4 af1 = *(const float4*)&As[cur][k][tm * 8 + 4];
            float aa[8] = {af0.x,af0.y,af0.z,af0.w,af1.x,af1.y,af1.z,af1.w};
            #pragma unroll
            for (int i = 0; i < 8; i++) {
                u64 a2 = splat2(aa[i]);
                ffma2(acc[i][0], a2, b0.x);
                ffma2(acc[i][1], a2, b0.y);
                ffma2(acc[i][2], a2, b1.x);
                ffma2(acc[i][3], a2, b1.y);
            }
        }
        if (c < 31) {
            const int nxt = cur ^ 1;
            float aa[8] = {av0.x,av0.y,av0.z,av0.w,av1.x,av1.y,av1.z,av1.w};
            float ww[8] = {wv0.x,wv0.y,wv0.z,wv0.w,wv1.x,wv1.y,wv1.z,wv1.w};
            #pragma unroll
            for (int i = 0; i < 8; i++) {
                As[nxt][lk8 + i][lrow] = aa[i];
                Bs[nxt][lk8 + i][lrow] = ww[i];
            }
            __syncthreads();
        }
    }

    // epilogue
    #pragma unroll
    for (int i = 0; i < 8; i++) {
        const int r  = row0 + tm * 8 + i;
        const int cc = col0 + tn * 8;
        float o[8];
        unpack2(acc[i][0], o[0], o[1]);
        unpack2(acc[i][1], o[2], o[3]);
        unpack2(acc[i][2], o[4], o[5]);
        unpack2(acc[i][3], o[6], o[7]);
        if (bias) {
            #pragma unroll
            for (int j = 0; j < 8; j++) o[j] += bias[cc + j];
        }
        float4 o0 = make_float4(o[0], o[1], o[2], o[3]);
        float4 o1 = make_float4(o[4], o[5], o[6], o[7]);
        *(float4*)(C + (size_t)r * Dn + cc)     = o0;
        *(float4*)(C + (size_t)r * Dn + cc + 4) = o1;
    }
}

// ----------------------------------------------------------------------------
// Stage 2: fused score + masked softmax (unchanged from R3).
// ----------------------------------------------------------------------------
__global__ void __launch_bounds__(128) score_softmax(
    const float* __restrict__ wq, const float* __restrict__ uh,
    const float* __restrict__ v, const int* __restrict__ lens,
    float* __restrict__ P, float* __restrict__ out_align, int write_align)
{
    const int t0 = blockIdx.x * 4;
    const int b  = blockIdx.y;
    const int tid = threadIdx.x, w = tid >> 5, lane = tid & 31;

    __shared__ __align__(16) float wq_sh[4][Dn];
    __shared__ __align__(16) float v_sh[Dn];
    __shared__ __align__(16) float uh_sh[Sn][36];

    for (int i = tid; i < 4 * (Dn/4); i += 128) {
        int t = i >> 7, j = i & 127;
        ((float4*)wq_sh[t])[j] = ((const float4*)(wq + ((size_t)(b*Tn + t0 + t)) * Dn))[j];
    }
    for (int i = tid; i < Dn/4; i += 128)
        ((float4*)v_sh)[i] = ((const float4*)v)[i];

    float a0=0.f,a1=0.f,a2=0.f,a3=0.f,a4=0.f,a5=0.f;

    for (int m0 = 0; m0 < Dn; m0 += 32) {
        __syncthreads();
        #pragma unroll
        for (int i = tid; i < Sn * 8; i += 128) {
            int row = i >> 3, mm = (i & 7) << 2;
            *(float4*)&uh_sh[row][mm] =
                *(const float4*)(uh + ((size_t)(b*Sn + row)) * Dn + m0 + mm);
        }
        __syncthreads();

        #pragma unroll
        for (int mm = 0; mm < 32; mm += 4) {
            float4 wv = *(const float4*)&wq_sh[w][m0 + mm];
            float4 vv = *(const float4*)&v_sh[m0 + mm];
            float4 u0 = *(const float4*)&uh_sh[lane      ][mm];
            float4 u1 = *(const float4*)&uh_sh[lane +  32][mm];
            float4 u2 = *(const float4*)&uh_sh[lane +  64][mm];
            float4 u3 = *(const float4*)&uh_sh[lane +  96][mm];
            float4 u4 = *(const float4*)&uh_sh[lane + 128][mm];
            float4 u5 = *(const float4*)&uh_sh[lane + 160][mm];
            a0 += tanh_fast(wv.x+u0.x)*vv.x; a0 += tanh_fast(wv.y+u0.y)*vv.y;
            a0 += tanh_fast(wv.z+u0.z)*vv.z; a0 += tanh_fast(wv.w+u0.w)*vv.w;
            a1 += tanh_fast(wv.x+u1.x)*vv.x; a1 += tanh_fast(wv.y+u1.y)*vv.y;
            a1 += tanh_fast(wv.z+u1.z)*vv.z; a1 += tanh_fast(wv.w+u1.w)*vv.w;
            a2 += tanh_fast(wv.x+u2.x)*vv.x; a2 += tanh_fast(wv.y+u2.y)*vv.y;
            a2 += tanh_fast(wv.z+u2.z)*vv.z; a2 += tanh_fast(wv.w+u2.w)*vv.w;
            a3 += tanh_fast(wv.x+u3.x)*vv.x; a3 += tanh_fast(wv.y+u3.y)*vv.y;
            a3 += tanh_fast(wv.z+u3.z)*vv.z; a3 += tanh_fast(wv.w+u3.w)*vv.w;
            a4 += tanh_fast(wv.x+u4.x)*vv.x; a4 += tanh_fast(wv.y+u4.y)*vv.y;
            a4 += tanh_fast(wv.z+u4.z)*vv.z; a4 += tanh_fast(wv.w+u4.w)*vv.w;
            a5 += tanh_fast(wv.x+u5.x)*vv.x; a5 += tanh_fast(wv.y+u5.y)*vv.y;
            a5 += tanh_fast(wv.z+u5.z)*vv.z; a5 += tanh_fast(wv.w+u5.w)*vv.w;
        }
    }

    const int L = lens[b];
    float vals[6] = {a0,a1,a2,a3,a4,a5};
    float mx = -INFINITY;
    #pragma unroll
    for (int k = 0; k < 6; k++) {
        if (lane + 32*k >= L) vals[k] = -INFINITY;
        mx = fmaxf(mx, vals[k]);
    }
    #pragma unroll
    for (int o = 16; o; o >>= 1) mx = fmaxf(mx, __shfl_xor_sync(0xFFFFFFFFu, mx, o));
    float sum = 0.f;
    #pragma unroll
    for (int k = 0; k < 6; k++) {
        float e = (vals[k] == -INFINITY) ? 0.f : __expf(vals[k] - mx);
        vals[k] = e; sum += e;
    }
    #pragma unroll
    for (int o = 16; o; o >>= 1) sum += __shfl_xor_sync(0xFFFFFFFFu, sum, o);
    const float inv = __fdividef(1.f, sum);

    const size_t rb = ((size_t)(b*Tn + t0 + w)) * Sn + lane;
    #pragma unroll
    for (int k = 0; k < 6; k++) {
        float p = vals[k] * inv;
        P[rb + 32*k] = p;
        if (write_align) out_align[rb + 32*k] = p;
    }
}

// ----------------------------------------------------------------------------
// Stage 3: out[b,t,:] = P[b] @ Wm[b] + base.  16x64 tile, 128 thr, 2x4 micro.
// ----------------------------------------------------------------------------
__global__ void __launch_bounds__(128) stage3_epilogue(
    const float* __restrict__ P, const float* __restrict__ Wm,
    const float* __restrict__ base, float* __restrict__ out)
{
    const int b  = blockIdx.z;
    const int m0 = blockIdx.y * 16;
    const int n0 = blockIdx.x * 64;
    const float* A  = P  + (size_t)b * Tn * Sn;
    const float* Bm = Wm + (size_t)b * Sn * Dn;

    __shared__ __align__(16) float As[16][20];
    __shared__ __align__(16) float Bs[16][68];

    const int tid = threadIdx.x;
    const int tm = tid >> 4;
    const int tn = tid & 15;

    float acc[2][4] = {};

    for (int k0 = 0; k0 < Sn; k0 += 16) {
        if (tid < 64) {
            int m = tid >> 2, k4 = (tid & 3) << 2;
            float4 a4 = *(const float4*)(A + (size_t)(m0 + m) * Sn + k0 + k4);
            As[k4+0][m] = a4.x; As[k4+1][m] = a4.y;
            As[k4+2][m] = a4.z; As[k4+3][m] = a4.w;
        }
        {
            int kk = tid >> 4, nn = (tid & 15) << 2;
            float4 b0 = *(const float4*)(Bm + (size_t)(k0 + kk)     * Dn + n0 + nn);
            float4 b1 = *(const float4*)(Bm + (size_t)(k0 + kk + 8) * Dn + n0 + nn);
            *(float4*)&Bs[kk][nn]     = b0;
            *(float4*)&Bs[kk + 8][nn] = b1;
        }
        __syncthreads();

        #pragma unroll
        for (int k = 0; k < 16; k++) {
            float a0 = As[k][tm*2], a1 = As[k][tm*2+1];
            float4 bv = *(const float4*)&Bs[k][tn*4];
            acc[0][0] += a0*bv.x; acc[0][1] += a0*bv.y; acc[0][2] += a0*bv.z; acc[0][3] += a0*bv.w;
            acc[1][0] += a1*bv.x; acc[1][1] += a1*bv.y; acc[1][2] += a1*bv.z; acc[1][3] += a1*bv.w;
        }
        __syncthreads();
    }

    #pragma unroll
    for (int i = 0; i < 2; i++) {
        const size_t r = (size_t)(b*Tn + m0 + tm*2 + i) * Dn + n0 + tn*4;
        float4 bb = *(const float4*)(base + r);
        float4 o;
        o.x = acc[i][0]+bb.x; o.y = acc[i][1]+bb.y;
        o.z = acc[i][2]+bb.z; o.w = acc[i][3]+bb.w;
        *(float4*)(out + r) = o;
    }
}

// ----------------------------------------------------------------------------
extern "C" void kernel_launch(void* const* d_in, const int* in_sizes, int n_in,
                              void* d_out, int out_size)
{
    const float* inputs = (const float*)d_in[0];
    const float* mems   = (const float*)d_in[1];
    const int*   lens   = (const int*)  d_in[2];
    const float* Wq     = (const float*)d_in[3];
    const float* Wc     = (const float*)d_in[4];
    const float* bc     = (const float*)d_in[5];
    const float* v      = (const float*)d_in[6];
    const float* Wout   = (const float*)d_in[7];
    const float* bout   = (const float*)d_in[8];
    float* out = (float*)d_out;

    float *wqb, *uhb, *wmb, *baseb, *pb;
    cudaGetSymbolAddress((void**)&wqb,   g_wq);
    cudaGetSymbolAddress((void**)&uhb,   g_uh);
    cudaGetSymbolAddress((void**)&wmb,   g_wm);
    cudaGetSymbolAddress((void**)&baseb, g_base);
    cudaGetSymbolAddress((void**)&pb,    g_p);

    const int attn_elems  = BT * Dn;
    const int align_elems = BT * Sn;
    const int write_align = (out_size >= attn_elems + align_elems) ? 1 : 0;
    float* out_align = out + attn_elems;

    // 1) wq, uh, Wm, base — 144 CTAs, one wave
    stage1_gemms<<<dim3(Dn/128, 36), 256>>>(
        inputs, mems, Wq, Wc, bc, Wout, bout, wqb, uhb, wmb, baseb);

    // 2) score + masked softmax — 192 CTAs
    score_softmax<<<dim3(Tn/4, Bn), 128>>>(wqb, uhb, v, lens, pb, out_align, write_align);

    // 3) out = P @ Wm + base — 384 CTAs
    stage3_epilogue<<<dim3(Dn/64, Tn/16, Bn), 128>>>(pb, wmb, baseb, out);
}

// round 6
// speedup vs baseline: 1.9091x; 1.9091x over previous
#include <cuda_runtime.h>
#include <cuda_bf16.h>
#include <math.h>
#include <cstdint>

#define Bn 8
#define Tn 96
#define Sn 192
#define Dn 512
#define BT (Bn*Tn)   // 768
#define BS (Bn*Sn)   // 1536

// Scratch
__device__ float g_wq  [BT * Dn];
__device__ float g_uh  [BS * Dn];
__device__ float g_wm  [BS * Dn];
__device__ float g_base[BT * Dn];
__device__ float g_p   [BT * Sn];

__device__ __forceinline__ float tanh_fast(float x) {
    float y;
    asm("tanh.approx.f32 %0, %1;" : "=f"(y) : "f"(x));
    return y;
}

__device__ __forceinline__ uint32_t smem_u32(const void* p) {
    uint32_t a;
    asm("{ .reg .u64 t; cvta.to.shared.u64 t, %1; cvt.u32.u64 %0, t; }" : "=r"(a) : "l"(p));
    return a;
}
__device__ __forceinline__ void ldsm4(uint32_t* r, uint32_t addr) {
    asm volatile("ldmatrix.sync.aligned.m8n8.x4.shared.b16 {%0,%1,%2,%3}, [%4];"
        : "=r"(r[0]), "=r"(r[1]), "=r"(r[2]), "=r"(r[3]) : "r"(addr));
}
__device__ __forceinline__ void ldsm2(uint32_t* r, uint32_t addr) {
    asm volatile("ldmatrix.sync.aligned.m8n8.x2.shared.b16 {%0,%1}, [%2];"
        : "=r"(r[0]), "=r"(r[1]) : "r"(addr));
}
__device__ __forceinline__ void mma16816(float* c, const uint32_t* a, const uint32_t* b) {
    asm volatile(
        "mma.sync.aligned.m16n8k16.row.col.f32.bf16.bf16.f32 "
        "{%0,%1,%2,%3}, {%4,%5,%6,%7}, {%8,%9}, {%0,%1,%2,%3};"
        : "+f"(c[0]), "+f"(c[1]), "+f"(c[2]), "+f"(c[3])
        : "r"(a[0]), "r"(a[1]), "r"(a[2]), "r"(a[3]), "r"(b[0]), "r"(b[1]));
}

// ----------------------------------------------------------------------------
// Stage 1 via mma.sync bf16 (hi/lo split, 3 terms): C = A @ W^T (+bias), K=512.
// CTA tile 128x128, 256 thr = 8 warps (2 M x 4 N), warp tile 64x32.
// K-chunk 32, single-buffered smem; smem row pitch 80B (40 bf16).
//   y<6  : wq   = inputs @ Wq^T
//   y<18 : uh   = mems @ Wc^T + bc
//   y<30 : Wm   = mems @ Wout[:, :512]^T
//   else : base = inputs @ Wout[:, 512:]^T + bout
// Grid (4, 36) = 144 CTAs.
// ----------------------------------------------------------------------------
#define PITCH 80
__global__ void __launch_bounds__(256, 1) stage1_mma(
    const float* __restrict__ inputs, const float* __restrict__ mems,
    const float* __restrict__ Wq, const float* __restrict__ Wc,
    const float* __restrict__ bc, const float* __restrict__ Wout,
    const float* __restrict__ bout,
    float* __restrict__ wq_o, float* __restrict__ uh_o,
    float* __restrict__ wm_o, float* __restrict__ base_o)
{
    const int y = blockIdx.y;
    const float* A; const float* W; int ldw; const float* bias; float* C; int row0;
    if (y < 6)       { A = inputs; W = Wq;         ldw = 512;  bias = nullptr; C = wq_o;   row0 = y * 128; }
    else if (y < 18) { A = mems;   W = Wc;         ldw = 512;  bias = bc;      C = uh_o;   row0 = (y-6)*128; }
    else if (y < 30) { A = mems;   W = Wout;       ldw = 1024; bias = nullptr; C = wm_o;   row0 = (y-18)*128; }
    else             { A = inputs; W = Wout + 512; ldw = 1024; bias = bout;    C = base_o; row0 = (y-30)*128; }
    const int col0 = blockIdx.x * 128;

    __shared__ __align__(16) unsigned char smAh[128 * PITCH];
    __shared__ __align__(16) unsigned char smAl[128 * PITCH];
    __shared__ __align__(16) unsigned char smBh[128 * PITCH];
    __shared__ __align__(16) unsigned char smBl[128 * PITCH];

    const int tid  = threadIdx.x;
    const int wid  = tid >> 5;
    const int lane = tid & 31;
    const int wM   = wid >> 2;      // 0..1
    const int wN   = wid & 3;       // 0..3

    // convert-phase mapping: one full 32-float row per thread
    const int  crow = tid & 127;
    const int  cisB = tid >> 7;
    const float* csrc = cisB ? (W + (size_t)(col0 + crow) * ldw)
                             : (A + (size_t)(row0 + crow) * Dn);
    unsigned char* sHi = (cisB ? smBh : smAh) + crow * PITCH;
    unsigned char* sLo = (cisB ? smBl : smAl) + crow * PITCH;

    // ldmatrix base addresses
    const uint32_t uAh = smem_u32(smAh), uAl = smem_u32(smAl);
    const uint32_t uBh = smem_u32(smBh), uBl = smem_u32(smBl);
    // A: rows wM*64 + mi*16 + (lane&15); k-half (lane>>4)*8 elems = *16 bytes
    const uint32_t aOffA = (uint32_t)((wM * 64 + (lane & 15)) * PITCH + ((lane >> 4) << 4));
    // B: rows wN*32 + ni*8 + (lane&7); k-half ((lane>>3)&1)*8 elems
    const uint32_t aOffB = (uint32_t)((wN * 32 + (lane & 7)) * PITCH + (((lane >> 3) & 1) << 4));

    float acc[4][4][4];
    #pragma unroll
    for (int i = 0; i < 4; i++)
        #pragma unroll
        for (int j = 0; j < 4; j++)
            #pragma unroll
            for (int q = 0; q < 4; q++) acc[i][j][q] = 0.f;

    for (int c = 0; c < 16; c++) {
        // ---- convert fp32 -> bf16 hi/lo for this 32-k chunk ----
        {
            const float4* p = (const float4*)(csrc + c * 32);
            uint32_t hi[16], lo[16];
            #pragma unroll
            for (int j = 0; j < 8; j++) {
                float4 f = p[j];
                __nv_bfloat162 h01 = __float22bfloat162_rn(make_float2(f.x, f.y));
                __nv_bfloat162 h23 = __float22bfloat162_rn(make_float2(f.z, f.w));
                float2 g01 = __bfloat1622float2(h01);
                float2 g23 = __bfloat1622float2(h23);
                __nv_bfloat162 l01 = __float22bfloat162_rn(make_float2(f.x - g01.x, f.y - g01.y));
                __nv_bfloat162 l23 = __float22bfloat162_rn(make_float2(f.z - g23.x, f.w - g23.y));
                hi[2*j]   = *(uint32_t*)&h01; hi[2*j+1] = *(uint32_t*)&h23;
                lo[2*j]   = *(uint32_t*)&l01; lo[2*j+1] = *(uint32_t*)&l23;
            }
            #pragma unroll
            for (int q = 0; q < 4; q++) {
                *(uint4*)(sHi + q * 16) = make_uint4(hi[4*q], hi[4*q+1], hi[4*q+2], hi[4*q+3]);
                *(uint4*)(sLo + q * 16) = make_uint4(lo[4*q], lo[4*q+1], lo[4*q+2], lo[4*q+3]);
            }
        }
        __syncthreads();

        // ---- MMA: 2 k16-steps x 3 terms ----
        #pragma unroll
        for (int ks = 0; ks < 2; ks++) {
            const uint32_t kb = (uint32_t)(ks * 32);
            uint32_t Ah[4][4], Bh[4][2];
            #pragma unroll
            for (int mi = 0; mi < 4; mi++)
                ldsm4(Ah[mi], uAh + aOffA + mi * (16 * PITCH) + kb);
            #pragma unroll
            for (int ni = 0; ni < 4; ni++)
                ldsm2(Bh[ni], uBh + aOffB + ni * (8 * PITCH) + kb);
            #pragma unroll
            for (int mi = 0; mi < 4; mi++)
                #pragma unroll
                for (int ni = 0; ni < 4; ni++)
                    mma16816(acc[mi][ni], Ah[mi], Bh[ni]);

            uint32_t Al[4][4];
            #pragma unroll
            for (int mi = 0; mi < 4; mi++)
                ldsm4(Al[mi], uAl + aOffA + mi * (16 * PITCH) + kb);
            #pragma unroll
            for (int mi = 0; mi < 4; mi++)
                #pragma unroll
                for (int ni = 0; ni < 4; ni++)
                    mma16816(acc[mi][ni], Al[mi], Bh[ni]);

            uint32_t Bl[4][2];
            #pragma unroll
            for (int ni = 0; ni < 4; ni++)
                ldsm2(Bl[ni], uBl + aOffB + ni * (8 * PITCH) + kb);
            #pragma unroll
            for (int mi = 0; mi < 4; mi++)
                #pragma unroll
                for (int ni = 0; ni < 4; ni++)
                    mma16816(acc[mi][ni], Ah[mi], Bl[ni]);
        }
        __syncthreads();
    }

    // ---- epilogue: acc regs -> gmem (+bias) ----
    const int erow = lane >> 2;          // 0..7
    const int ecol = (lane & 3) * 2;
    #pragma unroll
    for (int mi = 0; mi < 4; mi++) {
        const int r0 = row0 + wM * 64 + mi * 16 + erow;
        #pragma unroll
        for (int ni = 0; ni < 4; ni++) {
            const int cc = col0 + wN * 32 + ni * 8 + ecol;
            float b0 = 0.f, b1 = 0.f;
            if (bias) { b0 = bias[cc]; b1 = bias[cc + 1]; }
            float2 o0 = make_float2(acc[mi][ni][0] + b0, acc[mi][ni][1] + b1);
            float2 o1 = make_float2(acc[mi][ni][2] + b0, acc[mi][ni][3] + b1);
            *(float2*)(C + (size_t)r0 * Dn + cc)       = o0;
            *(float2*)(C + (size_t)(r0 + 8) * Dn + cc) = o1;
        }
    }
}

// ----------------------------------------------------------------------------
// Stage 2: fused score + masked softmax (unchanged from the 125us version).
// ----------------------------------------------------------------------------
__global__ void __launch_bounds__(128) score_softmax(
    const float* __restrict__ wq, const float* __restrict__ uh,
    const float* __restrict__ v, const int* __restrict__ lens,
    float* __restrict__ P, float* __restrict__ out_align, int write_align)
{
    const int t0 = blockIdx.x * 4;
    const int b  = blockIdx.y;
    const int tid = threadIdx.x, w = tid >> 5, lane = tid & 31;

    __shared__ __align__(16) float wq_sh[4][Dn];
    __shared__ __align__(16) float v_sh[Dn];
    __shared__ __align__(16) float uh_sh[Sn][36];

    for (int i = tid; i < 4 * (Dn/4); i += 128) {
        int t = i >> 7, j = i & 127;
        ((float4*)wq_sh[t])[j] = ((const float4*)(wq + ((size_t)(b*Tn + t0 + t)) * Dn))[j];
    }
    for (int i = tid; i < Dn/4; i += 128)
        ((float4*)v_sh)[i] = ((const float4*)v)[i];

    float a0=0.f,a1=0.f,a2=0.f,a3=0.f,a4=0.f,a5=0.f;

    for (int m0 = 0; m0 < Dn; m0 += 32) {
        __syncthreads();
        #pragma unroll
        for (int i = tid; i < Sn * 8; i += 128) {
            int row = i >> 3, mm = (i & 7) << 2;
            *(float4*)&uh_sh[row][mm] =
                *(const float4*)(uh + ((size_t)(b*Sn + row)) * Dn + m0 + mm);
        }
        __syncthreads();

        #pragma unroll
        for (int mm = 0; mm < 32; mm += 4) {
            float4 wv = *(const float4*)&wq_sh[w][m0 + mm];
            float4 vv = *(const float4*)&v_sh[m0 + mm];
            float4 u0 = *(const float4*)&uh_sh[lane      ][mm];
            float4 u1 = *(const float4*)&uh_sh[lane +  32][mm];
            float4 u2 = *(const float4*)&uh_sh[lane +  64][mm];
            float4 u3 = *(const float4*)&uh_sh[lane +  96][mm];
            float4 u4 = *(const float4*)&uh_sh[lane + 128][mm];
            float4 u5 = *(const float4*)&uh_sh[lane + 160][mm];
            a0 += tanh_fast(wv.x+u0.x)*vv.x; a0 += tanh_fast(wv.y+u0.y)*vv.y;
            a0 += tanh_fast(wv.z+u0.z)*vv.z; a0 += tanh_fast(wv.w+u0.w)*vv.w;
            a1 += tanh_fast(wv.x+u1.x)*vv.x; a1 += tanh_fast(wv.y+u1.y)*vv.y;
            a1 += tanh_fast(wv.z+u1.z)*vv.z; a1 += tanh_fast(wv.w+u1.w)*vv.w;
            a2 += tanh_fast(wv.x+u2.x)*vv.x; a2 += tanh_fast(wv.y+u2.y)*vv.y;
            a2 += tanh_fast(wv.z+u2.z)*vv.z; a2 += tanh_fast(wv.w+u2.w)*vv.w;
            a3 += tanh_fast(wv.x+u3.x)*vv.x; a3 += tanh_fast(wv.y+u3.y)*vv.y;
            a3 += tanh_fast(wv.z+u3.z)*vv.z; a3 += tanh_fast(wv.w+u3.w)*vv.w;
            a4 += tanh_fast(wv.x+u4.x)*vv.x; a4 += tanh_fast(wv.y+u4.y)*vv.y;
            a4 += tanh_fast(wv.z+u4.z)*vv.z; a4 += tanh_fast(wv.w+u4.w)*vv.w;
            a5 += tanh_fast(wv.x+u5.x)*vv.x; a5 += tanh_fast(wv.y+u5.y)*vv.y;
            a5 += tanh_fast(wv.z+u5.z)*vv.z; a5 += tanh_fast(wv.w+u5.w)*vv.w;
        }
    }

    const int L = lens[b];
    float vals[6] = {a0,a1,a2,a3,a4,a5};
    float mx = -INFINITY;
    #pragma unroll
    for (int k = 0; k < 6; k++) {
        if (lane + 32*k >= L) vals[k] = -INFINITY;
        mx = fmaxf(mx, vals[k]);
    }
    #pragma unroll
    for (int o = 16; o; o >>= 1) mx = fmaxf(mx, __shfl_xor_sync(0xFFFFFFFFu, mx, o));
    float sum = 0.f;
    #pragma unroll
    for (int k = 0; k < 6; k++) {
        float e = (vals[k] == -INFINITY) ? 0.f : __expf(vals[k] - mx);
        vals[k] = e; sum += e;
    }
    #pragma unroll
    for (int o = 16; o; o >>= 1) sum += __shfl_xor_sync(0xFFFFFFFFu, sum, o);
    const float inv = __fdividef(1.f, sum);

    const size_t rb = ((size_t)(b*Tn + t0 + w)) * Sn + lane;
    #pragma unroll
    for (int k = 0; k < 6; k++) {
        float p = vals[k] * inv;
        P[rb + 32*k] = p;
        if (write_align) out_align[rb + 32*k] = p;
    }
}

// ----------------------------------------------------------------------------
// Stage 3: out[b,t,:] = P[b] @ Wm[b] + base.  16x64 tile, 128 thr, 2x4 micro.
// ----------------------------------------------------------------------------
__global__ void __launch_bounds__(128) stage3_epilogue(
    const float* __restrict__ P, const float* __restrict__ Wm,
    const float* __restrict__ base, float* __restrict__ out)
{
    const int b  = blockIdx.z;
    const int m0 = blockIdx.y * 16;
    const int n0 = blockIdx.x * 64;
    const float* A  = P  + (size_t)b * Tn * Sn;
    const float* Bm = Wm + (size_t)b * Sn * Dn;

    __shared__ __align__(16) float As[16][20];
    __shared__ __align__(16) float Bs[16][68];

    const int tid = threadIdx.x;
    const int tm = tid >> 4;
    const int tn = tid & 15;

    float acc[2][4] = {};

    for (int k0 = 0; k0 < Sn; k0 += 16) {
        if (tid < 64) {
            int m = tid >> 2, k4 = (tid & 3) << 2;
            float4 a4 = *(const float4*)(A + (size_t)(m0 + m) * Sn + k0 + k4);
            As[k4+0][m] = a4.x; As[k4+1][m] = a4.y;
            As[k4+2][m] = a4.z; As[k4+3][m] = a4.w;
        }
        {
            int kk = tid >> 4, nn = (tid & 15) << 2;
            float4 b0 = *(const float4*)(Bm + (size_t)(k0 + kk)     * Dn + n0 + nn);
            float4 b1 = *(const float4*)(Bm + (size_t)(k0 + kk + 8) * Dn + n0 + nn);
            *(float4*)&Bs[kk][nn]     = b0;
            *(float4*)&Bs[kk + 8][nn] = b1;
        }
        __syncthreads();

        #pragma unroll
        for (int k = 0; k < 16; k++) {
            float a0 = As[k][tm*2], a1 = As[k][tm*2+1];
            float4 bv = *(const float4*)&Bs[k][tn*4];
            acc[0][0] += a0*bv.x; acc[0][1] += a0*bv.y; acc[0][2] += a0*bv.z; acc[0][3] += a0*bv.w;
            acc[1][0] += a1*bv.x; acc[1][1] += a1*bv.y; acc[1][2] += a1*bv.z; acc[1][3] += a1*bv.w;
        }
        __syncthreads();
    }

    #pragma unroll
    for (int i = 0; i < 2; i++) {
        const size_t r = (size_t)(b*Tn + m0 + tm*2 + i) * Dn + n0 + tn*4;
        float4 bb = *(const float4*)(base + r);
        float4 o;
        o.x = acc[i][0]+bb.x; o.y = acc[i][1]+bb.y;
        o.z = acc[i][2]+bb.z; o.w = acc[i][3]+bb.w;
        *(float4*)(out + r) = o;
    }
}

// ----------------------------------------------------------------------------
extern "C" void kernel_launch(void* const* d_in, const int* in_sizes, int n_in,
                              void* d_out, int out_size)
{
    const float* inputs = (const float*)d_in[0];
    const float* mems   = (const float*)d_in[1];
    const int*   lens   = (const int*)  d_in[2];
    const float* Wq     = (const float*)d_in[3];
    const float* Wc     = (const float*)d_in[4];
    const float* bc     = (const float*)d_in[5];
    const float* v      = (const float*)d_in[6];
    const float* Wout   = (const float*)d_in[7];
    const float* bout   = (const float*)d_in[8];
    float* out = (float*)d_out;

    float *wqb, *uhb, *wmb, *baseb, *pb;
    cudaGetSymbolAddress((void**)&wqb,   g_wq);
    cudaGetSymbolAddress((void**)&uhb,   g_uh);
    cudaGetSymbolAddress((void**)&wmb,   g_wm);
    cudaGetSymbolAddress((void**)&baseb, g_base);
    cudaGetSymbolAddress((void**)&pb,    g_p);

    const int attn_elems  = BT * Dn;
    const int align_elems = BT * Sn;
    const int write_align = (out_size >= attn_elems + align_elems) ? 1 : 0;
    float* out_align = out + attn_elems;

    // 1) wq, uh, Wm, base — mma.sync bf16 split, 144 CTAs
    stage1_mma<<<dim3(Dn/128, 36), 256>>>(
        inputs, mems, Wq, Wc, bc, Wout, bout, wqb, uhb, wmb, baseb);

    // 2) score + masked softmax — 192 CTAs
    score_softmax<<<dim3(Tn/4, Bn), 128>>>(wqb, uhb, v, lens, pb, out_align, write_align);

    // 3) out = P @ Wm + base — 384 CTAs
    stage3_epilogue<<<dim3(Dn/64, Tn/16, Bn), 128>>>(pb, wmb, baseb, out);
}

// round 8
// speedup vs baseline: 2.0046x; 1.0501x over previous
#include <cuda_runtime.h>
#include <cuda_bf16.h>
#include <math.h>
#include <cstdint>

#define Bn 8
#define Tn 96
#define Sn 192
#define Dn 512
#define BT (Bn*Tn)   // 768
#define BS (Bn*Sn)   // 1536

// Scratch
__device__ float g_wq  [BT * Dn];
__device__ float g_uh  [BS * Dn];
__device__ float g_wm  [BS * Dn];
__device__ float g_base[BT * Dn];
__device__ float g_p   [BT * Sn];

__device__ __forceinline__ float tanh_fast(float x) {
    float y;
    asm("tanh.approx.f32 %0, %1;" : "=f"(y) : "f"(x));
    return y;
}

__device__ __forceinline__ uint32_t smem_u32(const void* p) {
    uint32_t a;
    asm("{ .reg .u64 t; cvta.to.shared.u64 t, %1; cvt.u32.u64 %0, t; }" : "=r"(a) : "l"(p));
    return a;
}
__device__ __forceinline__ void ldsm4(uint32_t* r, uint32_t addr) {
    asm volatile("ldmatrix.sync.aligned.m8n8.x4.shared.b16 {%0,%1,%2,%3}, [%4];"
        : "=r"(r[0]), "=r"(r[1]), "=r"(r[2]), "=r"(r[3]) : "r"(addr));
}
__device__ __forceinline__ void ldsm2(uint32_t* r, uint32_t addr) {
    asm volatile("ldmatrix.sync.aligned.m8n8.x2.shared.b16 {%0,%1}, [%2];"
        : "=r"(r[0]), "=r"(r[1]) : "r"(addr));
}
__device__ __forceinline__ void mma16816(float* c, const uint32_t* a, const uint32_t* b) {
    asm volatile(
        "mma.sync.aligned.m16n8k16.row.col.f32.bf16.bf16.f32 "
        "{%0,%1,%2,%3}, {%4,%5,%6,%7}, {%8,%9}, {%0,%1,%2,%3};"
        : "+f"(c[0]), "+f"(c[1]), "+f"(c[2]), "+f"(c[3])
        : "r"(a[0]), "r"(a[1]), "r"(a[2]), "r"(a[3]), "r"(b[0]), "r"(b[1]));
}

// ----------------------------------------------------------------------------
// Stage 1 via mma.sync bf16 (hi/lo split, 3 terms): C = A @ W^T (+bias), K=512.
// CTA tile 128x128, 256 thr = 8 warps (2 M x 4 N), warp tile 64x32.
// K-chunk 32; software-pipelined: LDG for chunk c+1 issued before MMA of c,
// so global-load latency hides under tensor work. smem row pitch 80B.
// Grid (4, 36) = 144 CTAs.
// ----------------------------------------------------------------------------
#define PITCH 80
__global__ void __launch_bounds__(256, 1) stage1_mma(
    const float* __restrict__ inputs, const float* __restrict__ mems,
    const float* __restrict__ Wq, const float* __restrict__ Wc,
    const float* __restrict__ bc, const float* __restrict__ Wout,
    const float* __restrict__ bout,
    float* __restrict__ wq_o, float* __restrict__ uh_o,
    float* __restrict__ wm_o, float* __restrict__ base_o)
{
    const int y = blockIdx.y;
    const float* A; const float* W; int ldw; const float* bias; float* C; int row0;
    if (y < 6)       { A = inputs; W = Wq;         ldw = 512;  bias = nullptr; C = wq_o;   row0 = y * 128; }
    else if (y < 18) { A = mems;   W = Wc;         ldw = 512;  bias = bc;      C = uh_o;   row0 = (y-6)*128; }
    else if (y < 30) { A = mems;   W = Wout;       ldw = 1024; bias = nullptr; C = wm_o;   row0 = (y-18)*128; }
    else             { A = inputs; W = Wout + 512; ldw = 1024; bias = bout;    C = base_o; row0 = (y-30)*128; }
    const int col0 = blockIdx.x * 128;

    __shared__ __align__(16) unsigned char smAh[128 * PITCH];
    __shared__ __align__(16) unsigned char smAl[128 * PITCH];
    __shared__ __align__(16) unsigned char smBh[128 * PITCH];
    __shared__ __align__(16) unsigned char smBl[128 * PITCH];

    const int tid  = threadIdx.x;
    const int wid  = tid >> 5;
    const int lane = tid & 31;
    const int wM   = wid >> 2;      // 0..1
    const int wN   = wid & 3;       // 0..3

    // convert-phase mapping: one full 32-float row per thread
    const int  crow = tid & 127;
    const int  cisB = tid >> 7;
    const float4* csrc4 = (const float4*)(cisB ? (W + (size_t)(col0 + crow) * ldw)
                                               : (A + (size_t)(row0 + crow) * Dn));
    unsigned char* sHi = (cisB ? smBh : smAh) + crow * PITCH;
    unsigned char* sLo = (cisB ? smBl : smAl) + crow * PITCH;

    // ldmatrix base addresses
    const uint32_t uAh = smem_u32(smAh), uAl = smem_u32(smAl);
    const uint32_t uBh = smem_u32(smBh), uBl = smem_u32(smBl);
    const uint32_t aOffA = (uint32_t)((wM * 64 + (lane & 15)) * PITCH + ((lane >> 4) << 4));
    const uint32_t aOffB = (uint32_t)((wN * 32 + (lane & 7)) * PITCH + (((lane >> 3) & 1) << 4));

    float acc[4][4][4];
    #pragma unroll
    for (int i = 0; i < 4; i++)
        #pragma unroll
        for (int j = 0; j < 4; j++)
            #pragma unroll
            for (int q = 0; q < 4; q++) acc[i][j][q] = 0.f;

    // prefetch chunk 0
    float4 pre[8];
    #pragma unroll
    for (int j = 0; j < 8; j++) pre[j] = csrc4[j];

    for (int c = 0; c < 16; c++) {
        // ---- convert prefetched fp32 -> bf16 hi/lo, store to smem ----
        {
            uint32_t hi[16], lo[16];
            #pragma unroll
            for (int j = 0; j < 8; j++) {
                float4 f = pre[j];
                __nv_bfloat162 h01 = __float22bfloat162_rn(make_float2(f.x, f.y));
                __nv_bfloat162 h23 = __float22bfloat162_rn(make_float2(f.z, f.w));
                float2 g01 = __bfloat1622float2(h01);
                float2 g23 = __bfloat1622float2(h23);
                __nv_bfloat162 l01 = __float22bfloat162_rn(make_float2(f.x - g01.x, f.y - g01.y));
                __nv_bfloat162 l23 = __float22bfloat162_rn(make_float2(f.z - g23.x, f.w - g23.y));
                hi[2*j]   = *(uint32_t*)&h01; hi[2*j+1] = *(uint32_t*)&h23;
                lo[2*j]   = *(uint32_t*)&l01; lo[2*j+1] = *(uint32_t*)&l23;
            }
            #pragma unroll
            for (int q = 0; q < 4; q++) {
                *(uint4*)(sHi + q * 16) = make_uint4(hi[4*q], hi[4*q+1], hi[4*q+2], hi[4*q+3]);
                *(uint4*)(sLo + q * 16) = make_uint4(lo[4*q], lo[4*q+1], lo[4*q+2], lo[4*q+3]);
            }
        }
        __syncthreads();

        // ---- issue LDGs for next chunk (latency hides under MMA below) ----
        if (c < 15) {
            #pragma unroll
            for (int j = 0; j < 8; j++) pre[j] = csrc4[(c + 1) * 8 + j];
        }

        // ---- MMA: 2 k16-steps x 3 terms ----
        #pragma unroll
        for (int ks = 0; ks < 2; ks++) {
            const uint32_t kb = (uint32_t)(ks * 32);
            uint32_t Ah[4][4], Bh[4][2];
            #pragma unroll
            for (int mi = 0; mi < 4; mi++)
                ldsm4(Ah[mi], uAh + aOffA + mi * (16 * PITCH) + kb);
            #pragma unroll
            for (int ni = 0; ni < 4; ni++)
                ldsm2(Bh[ni], uBh + aOffB + ni * (8 * PITCH) + kb);
            #pragma unroll
            for (int mi = 0; mi < 4; mi++)
                #pragma unroll
                for (int ni = 0; ni < 4; ni++)
                    mma16816(acc[mi][ni], Ah[mi], Bh[ni]);

            uint32_t Al[4][4];
            #pragma unroll
            for (int mi = 0; mi < 4; mi++)
                ldsm4(Al[mi], uAl + aOffA + mi * (16 * PITCH) + kb);
            #pragma unroll
            for (int mi = 0; mi < 4; mi++)
                #pragma unroll
                for (int ni = 0; ni < 4; ni++)
                    mma16816(acc[mi][ni], Al[mi], Bh[ni]);

            uint32_t Bl[4][2];
            #pragma unroll
            for (int ni = 0; ni < 4; ni++)
                ldsm2(Bl[ni], uBl + aOffB + ni * (8 * PITCH) + kb);
            #pragma unroll
            for (int mi = 0; mi < 4; mi++)
                #pragma unroll
                for (int ni = 0; ni < 4; ni++)
                    mma16816(acc[mi][ni], Ah[mi], Bl[ni]);
        }
        __syncthreads();
    }

    // ---- epilogue: acc regs -> gmem (+bias) ----
    const int erow = lane >> 2;
    const int ecol = (lane & 3) * 2;
    #pragma unroll
    for (int mi = 0; mi < 4; mi++) {
        const int r0 = row0 + wM * 64 + mi * 16 + erow;
        #pragma unroll
        for (int ni = 0; ni < 4; ni++) {
            const int cc = col0 + wN * 32 + ni * 8 + ecol;
            float b0 = 0.f, b1 = 0.f;
            if (bias) { b0 = bias[cc]; b1 = bias[cc + 1]; }
            float2 o0 = make_float2(acc[mi][ni][0] + b0, acc[mi][ni][1] + b1);
            float2 o1 = make_float2(acc[mi][ni][2] + b0, acc[mi][ni][3] + b1);
            *(float2*)(C + (size_t)r0 * Dn + cc)       = o0;
            *(float2*)(C + (size_t)(r0 + 8) * Dn + cc) = o1;
        }
    }
}

// ----------------------------------------------------------------------------
// Stage 2: fused score + masked softmax (unchanged).
// ----------------------------------------------------------------------------
__global__ void __launch_bounds__(128) score_softmax(
    const float* __restrict__ wq, const float* __restrict__ uh,
    const float* __restrict__ v, const int* __restrict__ lens,
    float* __restrict__ P, float* __restrict__ out_align, int write_align)
{
    const int t0 = blockIdx.x * 4;
    const int b  = blockIdx.y;
    const int tid = threadIdx.x, w = tid >> 5, lane = tid & 31;

    __shared__ __align__(16) float wq_sh[4][Dn];
    __shared__ __align__(16) float v_sh[Dn];
    __shared__ __align__(16) float uh_sh[Sn][36];

    for (int i = tid; i < 4 * (Dn/4); i += 128) {
        int t = i >> 7, j = i & 127;
        ((float4*)wq_sh[t])[j] = ((const float4*)(wq + ((size_t)(b*Tn + t0 + t)) * Dn))[j];
    }
    for (int i = tid; i < Dn/4; i += 128)
        ((float4*)v_sh)[i] = ((const float4*)v)[i];

    float a0=0.f,a1=0.f,a2=0.f,a3=0.f,a4=0.f,a5=0.f;

    for (int m0 = 0; m0 < Dn; m0 += 32) {
        __syncthreads();
        #pragma unroll
        for (int i = tid; i < Sn * 8; i += 128) {
            int row = i >> 3, mm = (i & 7) << 2;
            *(float4*)&uh_sh[row][mm] =
                *(const float4*)(uh + ((size_t)(b*Sn + row)) * Dn + m0 + mm);
        }
        __syncthreads();

        #pragma unroll
        for (int mm = 0; mm < 32; mm += 4) {
            float4 wv = *(const float4*)&wq_sh[w][m0 + mm];
            float4 vv = *(const float4*)&v_sh[m0 + mm];
            float4 u0 = *(const float4*)&uh_sh[lane      ][mm];
            float4 u1 = *(const float4*)&uh_sh[lane +  32][mm];
            float4 u2 = *(const float4*)&uh_sh[lane +  64][mm];
            float4 u3 = *(const float4*)&uh_sh[lane +  96][mm];
            float4 u4 = *(const float4*)&uh_sh[lane + 128][mm];
            float4 u5 = *(const float4*)&uh_sh[lane + 160][mm];
            a0 += tanh_fast(wv.x+u0.x)*vv.x; a0 += tanh_fast(wv.y+u0.y)*vv.y;
            a0 += tanh_fast(wv.z+u0.z)*vv.z; a0 += tanh_fast(wv.w+u0.w)*vv.w;
            a1 += tanh_fast(wv.x+u1.x)*vv.x; a1 += tanh_fast(wv.y+u1.y)*vv.y;
            a1 += tanh_fast(wv.z+u1.z)*vv.z; a1 += tanh_fast(wv.w+u1.w)*vv.w;
            a2 += tanh_fast(wv.x+u2.x)*vv.x; a2 += tanh_fast(wv.y+u2.y)*vv.y;
            a2 += tanh_fast(wv.z+u2.z)*vv.z; a2 += tanh_fast(wv.w+u2.w)*vv.w;
            a3 += tanh_fast(wv.x+u3.x)*vv.x; a3 += tanh_fast(wv.y+u3.y)*vv.y;
            a3 += tanh_fast(wv.z+u3.z)*vv.z; a3 += tanh_fast(wv.w+u3.w)*vv.w;
            a4 += tanh_fast(wv.x+u4.x)*vv.x; a4 += tanh_fast(wv.y+u4.y)*vv.y;
            a4 += tanh_fast(wv.z+u4.z)*vv.z; a4 += tanh_fast(wv.w+u4.w)*vv.w;
            a5 += tanh_fast(wv.x+u5.x)*vv.x; a5 += tanh_fast(wv.y+u5.y)*vv.y;
            a5 += tanh_fast(wv.z+u5.z)*vv.z; a5 += tanh_fast(wv.w+u5.w)*vv.w;
        }
    }

    const int L = lens[b];
    float vals[6] = {a0,a1,a2,a3,a4,a5};
    float mx = -INFINITY;
    #pragma unroll
    for (int k = 0; k < 6; k++) {
        if (lane + 32*k >= L) vals[k] = -INFINITY;
        mx = fmaxf(mx, vals[k]);
    }
    #pragma unroll
    for (int o = 16; o; o >>= 1) mx = fmaxf(mx, __shfl_xor_sync(0xFFFFFFFFu, mx, o));
    float sum = 0.f;
    #pragma unroll
    for (int k = 0; k < 6; k++) {
        float e = (vals[k] == -INFINITY) ? 0.f : __expf(vals[k] - mx);
        vals[k] = e; sum += e;
    }
    #pragma unroll
    for (int o = 16; o; o >>= 1) sum += __shfl_xor_sync(0xFFFFFFFFu, sum, o);
    const float inv = __fdividef(1.f, sum);

    const size_t rb = ((size_t)(b*Tn + t0 + w)) * Sn + lane;
    #pragma unroll
    for (int k = 0; k < 6; k++) {
        float p = vals[k] * inv;
        P[rb + 32*k] = p;
        if (write_align) out_align[rb + 32*k] = p;
    }
}

// ----------------------------------------------------------------------------
// Stage 3: out[b,t,:] = P[b] @ Wm[b] + base (unchanged).
// ----------------------------------------------------------------------------
__global__ void __launch_bounds__(128) stage3_epilogue(
    const float* __restrict__ P, const float* __restrict__ Wm,
    const float* __restrict__ base, float* __restrict__ out)
{
    const int b  = blockIdx.z;
    const int m0 = blockIdx.y * 16;
    const int n0 = blockIdx.x * 64;
    const float* A  = P  + (size_t)b * Tn * Sn;
    const float* Bm = Wm + (size_t)b * Sn * Dn;

    __shared__ __align__(16) float As[16][20];
    __shared__ __align__(16) float Bs[16][68];

    const int tid = threadIdx.x;
    const int tm = tid >> 4;
    const int tn = tid & 15;

    float acc[2][4] = {};

    for (int k0 = 0; k0 < Sn; k0 += 16) {
        if (tid < 64) {
            int m = tid >> 2, k4 = (tid & 3) << 2;
            float4 a4 = *(const float4*)(A + (size_t)(m0 + m) * Sn + k0 + k4);
            As[k4+0][m] = a4.x; As[k4+1][m] = a4.y;
            As[k4+2][m] = a4.z; As[k4+3][m] = a4.w;
        }
        {
            int kk = tid >> 4, nn = (tid & 15) << 2;
            float4 b0 = *(const float4*)(Bm + (size_t)(k0 + kk)     * Dn + n0 + nn);
            float4 b1 = *(const float4*)(Bm + (size_t)(k0 + kk + 8) * Dn + n0 + nn);
            *(float4*)&Bs[kk][nn]     = b0;
            *(float4*)&Bs[kk + 8][nn] = b1;
        }
        __syncthreads();

        #pragma unroll
        for (int k = 0; k < 16; k++) {
            float a0 = As[k][tm*2], a1 = As[k][tm*2+1];
            float4 bv = *(const float4*)&Bs[k][tn*4];
            acc[0][0] += a0*bv.x; acc[0][1] += a0*bv.y; acc[0][2] += a0*bv.z; acc[0][3] += a0*bv.w;
            acc[1][0] += a1*bv.x; acc[1][1] += a1*bv.y; acc[1][2] += a1*bv.z; acc[1][3] += a1*bv.w;
        }
        __syncthreads();
    }

    #pragma unroll
    for (int i = 0; i < 2; i++) {
        const size_t r = (size_t)(b*Tn + m0 + tm*2 + i) * Dn + n0 + tn*4;
        float4 bb = *(const float4*)(base + r);
        float4 o;
        o.x = acc[i][0]+bb.x; o.y = acc[i][1]+bb.y;
        o.z = acc[i][2]+bb.z; o.w = acc[i][3]+bb.w;
        *(float4*)(out + r) = o;
    }
}

// ----------------------------------------------------------------------------
extern "C" void kernel_launch(void* const* d_in, const int* in_sizes, int n_in,
                              void* d_out, int out_size)
{
    const float* inputs = (const float*)d_in[0];
    const float* mems   = (const float*)d_in[1];
    const int*   lens   = (const int*)  d_in[2];
    const float* Wq     = (const float*)d_in[3];
    const float* Wc     = (const float*)d_in[4];
    const float* bc     = (const float*)d_in[5];
    const float* v      = (const float*)d_in[6];
    const float* Wout   = (const float*)d_in[7];
    const float* bout   = (const float*)d_in[8];
    float* out = (float*)d_out;

    float *wqb, *uhb, *wmb, *baseb, *pb;
    cudaGetSymbolAddress((void**)&wqb,   g_wq);
    cudaGetSymbolAddress((void**)&uhb,   g_uh);
    cudaGetSymbolAddress((void**)&wmb,   g_wm);
    cudaGetSymbolAddress((void**)&baseb, g_base);
    cudaGetSymbolAddress((void**)&pb,    g_p);

    const int attn_elems  = BT * Dn;
    const int align_elems = BT * Sn;
    const int write_align = (out_size >= attn_elems + align_elems) ? 1 : 0;
    float* out_align = out + attn_elems;

    // 1) wq, uh, Wm, base — pipelined mma.sync bf16 split, 144 CTAs
    stage1_mma<<<dim3(Dn/128, 36), 256>>>(
        inputs, mems, Wq, Wc, bc, Wout, bout, wqb, uhb, wmb, baseb);

    // 2) score + masked softmax — 192 CTAs
    score_softmax<<<dim3(Tn/4, Bn), 128>>>(wqb, uhb, v, lens, pb, out_align, write_align);

    // 3) out = P @ Wm + base — 384 CTAs
    stage3_epilogue<<<dim3(Dn/64, Tn/16, Bn), 128>>>(pb, wmb, baseb, out);
}

// round 9
// speedup vs baseline: 2.0884x; 1.0418x over previous
#include <cuda_runtime.h>
#include <cuda_bf16.h>
#include <math.h>
#include <cstdint>

#define Bn 8
#define Tn 96
#define Sn 192
#define Dn 512
#define BT (Bn*Tn)   // 768
#define BS (Bn*Sn)   // 1536

// Scratch
__device__ float g_wq  [BT * Dn];
__device__ float g_uh  [BS * Dn];
__device__ float g_wm  [BS * Dn];
__device__ float g_base[BT * Dn];
__device__ float g_p   [BT * Sn];

__device__ __forceinline__ float tanh_fast(float x) {
    float y;
    asm("tanh.approx.f32 %0, %1;" : "=f"(y) : "f"(x));
    return y;
}

__device__ __forceinline__ uint32_t smem_u32(const void* p) {
    uint32_t a;
    asm("{ .reg .u64 t; cvta.to.shared.u64 t, %1; cvt.u32.u64 %0, t; }" : "=r"(a) : "l"(p));
    return a;
}
__device__ __forceinline__ void ldsm4(uint32_t* r, uint32_t addr) {
    asm volatile("ldmatrix.sync.aligned.m8n8.x4.shared.b16 {%0,%1,%2,%3}, [%4];"
        : "=r"(r[0]), "=r"(r[1]), "=r"(r[2]), "=r"(r[3]) : "r"(addr));
}
__device__ __forceinline__ void ldsm2(uint32_t* r, uint32_t addr) {
    asm volatile("ldmatrix.sync.aligned.m8n8.x2.shared.b16 {%0,%1}, [%2];"
        : "=r"(r[0]), "=r"(r[1]) : "r"(addr));
}
__device__ __forceinline__ void mma16816(float* c, const uint32_t* a, const uint32_t* b) {
    asm volatile(
        "mma.sync.aligned.m16n8k16.row.col.f32.bf16.bf16.f32 "
        "{%0,%1,%2,%3}, {%4,%5,%6,%7}, {%8,%9}, {%0,%1,%2,%3};"
        : "+f"(c[0]), "+f"(c[1]), "+f"(c[2]), "+f"(c[3])
        : "r"(a[0]), "r"(a[1]), "r"(a[2]), "r"(a[3]), "r"(b[0]), "r"(b[1]));
}

// ----------------------------------------------------------------------------
// Stage 1 via mma.sync bf16 (hi/lo split, 3 terms): C = A @ W^T (+bias), K=512.
// CTA tile 128x128, 256 thr = 8 warps (2 M x 4 N), warp tile 64x32.
// K-chunk 32; DOUBLE-BUFFERED smem: per chunk LDG(c+1) -> MMA(c) ->
// cvt+STS(c+1 into alt buffer) -> one barrier. smem row pitch 80B.
// Grid (4, 36) = 144 CTAs.
// ----------------------------------------------------------------------------
#define PITCH 80
#define TILEB 10240          // 128 * PITCH
#define OAH 0
#define OAL 10240
#define OBH 20480
#define OBL 30720
#define BUFB 40960
#define S1_SMEM (2 * BUFB)   // 81920

__global__ void __launch_bounds__(256, 1) stage1_mma(
    const float* __restrict__ inputs, const float* __restrict__ mems,
    const float* __restrict__ Wq, const float* __restrict__ Wc,
    const float* __restrict__ bc, const float* __restrict__ Wout,
    const float* __restrict__ bout,
    float* __restrict__ wq_o, float* __restrict__ uh_o,
    float* __restrict__ wm_o, float* __restrict__ base_o)
{
    extern __shared__ __align__(16) unsigned char smem[];
    const uint32_t sb = smem_u32(smem);

    const int y = blockIdx.y;
    const float* A; const float* W; int ldw; const float* bias; float* C; int row0;
    if (y < 6)       { A = inputs; W = Wq;         ldw = 512;  bias = nullptr; C = wq_o;   row0 = y * 128; }
    else if (y < 18) { A = mems;   W = Wc;         ldw = 512;  bias = bc;      C = uh_o;   row0 = (y-6)*128; }
    else if (y < 30) { A = mems;   W = Wout;       ldw = 1024; bias = nullptr; C = wm_o;   row0 = (y-18)*128; }
    else             { A = inputs; W = Wout + 512; ldw = 1024; bias = bout;    C = base_o; row0 = (y-30)*128; }
    const int col0 = blockIdx.x * 128;

    const int tid  = threadIdx.x;
    const int wid  = tid >> 5;
    const int lane = tid & 31;
    const int wM   = wid >> 2;      // 0..1
    const int wN   = wid & 3;       // 0..3

    // convert-phase mapping: one full 32-float row per thread
    const int  crow = tid & 127;
    const int  cisB = tid >> 7;
    const float4* csrc4 = (const float4*)(cisB ? (W + (size_t)(col0 + crow) * ldw)
                                               : (A + (size_t)(row0 + crow) * Dn));
    const int cvtOff = (cisB ? OBH : OAH) + crow * PITCH;   // hi; lo = +10240

    // ldmatrix per-warp offsets (relative to buffer base)
    const uint32_t aOffA = (uint32_t)((wM * 64 + (lane & 15)) * PITCH + ((lane >> 4) << 4));
    const uint32_t aOffB = (uint32_t)((wN * 32 + (lane & 7)) * PITCH + (((lane >> 3) & 1) << 4));

    float acc[4][4][4];
    #pragma unroll
    for (int i = 0; i < 4; i++)
        #pragma unroll
        for (int j = 0; j < 4; j++)
            #pragma unroll
            for (int q = 0; q < 4; q++) acc[i][j][q] = 0.f;

    float4 pre[8];
    #pragma unroll
    for (int j = 0; j < 8; j++) pre[j] = csrc4[j];

    // convert pre -> buffer 0
    {
        unsigned char* sHi = smem + cvtOff;
        unsigned char* sLo = sHi + 10240;
        uint32_t hi[16], lo[16];
        #pragma unroll
        for (int j = 0; j < 8; j++) {
            float4 f = pre[j];
            __nv_bfloat162 h01 = __float22bfloat162_rn(make_float2(f.x, f.y));
            __nv_bfloat162 h23 = __float22bfloat162_rn(make_float2(f.z, f.w));
            float2 g01 = __bfloat1622float2(h01);
            float2 g23 = __bfloat1622float2(h23);
            __nv_bfloat162 l01 = __float22bfloat162_rn(make_float2(f.x - g01.x, f.y - g01.y));
            __nv_bfloat162 l23 = __float22bfloat162_rn(make_float2(f.z - g23.x, f.w - g23.y));
            hi[2*j]   = *(uint32_t*)&h01; hi[2*j+1] = *(uint32_t*)&h23;
            lo[2*j]   = *(uint32_t*)&l01; lo[2*j+1] = *(uint32_t*)&l23;
        }
        #pragma unroll
        for (int q = 0; q < 4; q++) {
            *(uint4*)(sHi + q * 16) = make_uint4(hi[4*q], hi[4*q+1], hi[4*q+2], hi[4*q+3]);
            *(uint4*)(sLo + q * 16) = make_uint4(lo[4*q], lo[4*q+1], lo[4*q+2], lo[4*q+3]);
        }
    }
    __syncthreads();

    for (int c = 0; c < 16; c++) {
        const int cur = c & 1;
        const uint32_t bufc = sb + cur * BUFB;

        // LDG for next chunk (arrives while MMA below runs)
        if (c < 15) {
            #pragma unroll
            for (int j = 0; j < 8; j++) pre[j] = csrc4[(c + 1) * 8 + j];
        }

        // ---- MMA on current buffer: 2 k16-steps x 3 terms ----
        #pragma unroll
        for (int ks = 0; ks < 2; ks++) {
            const uint32_t kb = (uint32_t)(ks * 32);
            uint32_t Ah[4][4], Bh[4][2];
            #pragma unroll
            for (int mi = 0; mi < 4; mi++)
                ldsm4(Ah[mi], bufc + OAH + aOffA + mi * (16 * PITCH) + kb);
            #pragma unroll
            for (int ni = 0; ni < 4; ni++)
                ldsm2(Bh[ni], bufc + OBH + aOffB + ni * (8 * PITCH) + kb);
            #pragma unroll
            for (int mi = 0; mi < 4; mi++)
                #pragma unroll
                for (int ni = 0; ni < 4; ni++)
                    mma16816(acc[mi][ni], Ah[mi], Bh[ni]);

            uint32_t Al[4][4];
            #pragma unroll
            for (int mi = 0; mi < 4; mi++)
                ldsm4(Al[mi], bufc + OAL + aOffA + mi * (16 * PITCH) + kb);
            #pragma unroll
            for (int mi = 0; mi < 4; mi++)
                #pragma unroll
                for (int ni = 0; ni < 4; ni++)
                    mma16816(acc[mi][ni], Al[mi], Bh[ni]);

            uint32_t Bl[4][2];
            #pragma unroll
            for (int ni = 0; ni < 4; ni++)
                ldsm2(Bl[ni], bufc + OBL + aOffB + ni * (8 * PITCH) + kb);
            #pragma unroll
            for (int mi = 0; mi < 4; mi++)
                #pragma unroll
                for (int ni = 0; ni < 4; ni++)
                    mma16816(acc[mi][ni], Ah[mi], Bl[ni]);
        }

        // ---- convert prefetched chunk into the other buffer ----
        if (c < 15) {
            unsigned char* sHi = smem + (cur ^ 1) * BUFB + cvtOff;
            unsigned char* sLo = sHi + 10240;
            uint32_t hi[16], lo[16];
            #pragma unroll
            for (int j = 0; j < 8; j++) {
                float4 f = pre[j];
                __nv_bfloat162 h01 = __float22bfloat162_rn(make_float2(f.x, f.y));
                __nv_bfloat162 h23 = __float22bfloat162_rn(make_float2(f.z, f.w));
                float2 g01 = __bfloat1622float2(h01);
                float2 g23 = __bfloat1622float2(h23);
                __nv_bfloat162 l01 = __float22bfloat162_rn(make_float2(f.x - g01.x, f.y - g01.y));
                __nv_bfloat162 l23 = __float22bfloat162_rn(make_float2(f.z - g23.x, f.w - g23.y));
                hi[2*j]   = *(uint32_t*)&h01; hi[2*j+1] = *(uint32_t*)&h23;
                lo[2*j]   = *(uint32_t*)&l01; lo[2*j+1] = *(uint32_t*)&l23;
            }
            #pragma unroll
            for (int q = 0; q < 4; q++) {
                *(uint4*)(sHi + q * 16) = make_uint4(hi[4*q], hi[4*q+1], hi[4*q+2], hi[4*q+3]);
                *(uint4*)(sLo + q * 16) = make_uint4(lo[4*q], lo[4*q+1], lo[4*q+2], lo[4*q+3]);
            }
        }
        __syncthreads();
    }

    // ---- epilogue: acc regs -> gmem (+bias) ----
    const int erow = lane >> 2;
    const int ecol = (lane & 3) * 2;
    #pragma unroll
    for (int mi = 0; mi < 4; mi++) {
        const int r0 = row0 + wM * 64 + mi * 16 + erow;
        #pragma unroll
        for (int ni = 0; ni < 4; ni++) {
            const int cc = col0 + wN * 32 + ni * 8 + ecol;
            float b0 = 0.f, b1 = 0.f;
            if (bias) { b0 = bias[cc]; b1 = bias[cc + 1]; }
            float2 o0 = make_float2(acc[mi][ni][0] + b0, acc[mi][ni][1] + b1);
            float2 o1 = make_float2(acc[mi][ni][2] + b0, acc[mi][ni][3] + b1);
            *(float2*)(C + (size_t)r0 * Dn + cc)       = o0;
            *(float2*)(C + (size_t)(r0 + 8) * Dn + cc) = o1;
        }
    }
}

// ----------------------------------------------------------------------------
// Stage 2: fused score + masked softmax, 256 threads = 8 warps.
// warp w -> t = t0 + (w>>1), s-half = w&1; lane covers 3 s values.
// Softmax combined across warp pairs via smem.
// ----------------------------------------------------------------------------
__global__ void __launch_bounds__(256) score_softmax(
    const float* __restrict__ wq, const float* __restrict__ uh,
    const float* __restrict__ v, const int* __restrict__ lens,
    float* __restrict__ P, float* __restrict__ out_align, int write_align)
{
    const int t0 = blockIdx.x * 4;
    const int b  = blockIdx.y;
    const int tid = threadIdx.x, w = tid >> 5, lane = tid & 31;
    const int tloc = w >> 1;            // 0..3
    const int sh   = w & 1;             // s-half
    const int sbas = sh * 96 + lane;

    __shared__ __align__(16) float wq_sh[4][Dn];
    __shared__ __align__(16) float v_sh[Dn];
    __shared__ __align__(16) float uh_sh[Sn][36];
    __shared__ float rmax[8], rsum[8];

    for (int i = tid; i < 4 * (Dn/4); i += 256) {
        int t = i >> 7, j = i & 127;
        ((float4*)wq_sh[t])[j] = ((const float4*)(wq + ((size_t)(b*Tn + t0 + t)) * Dn))[j];
    }
    for (int i = tid; i < Dn/4; i += 256)
        ((float4*)v_sh)[i] = ((const float4*)v)[i];

    float a0=0.f, a1=0.f, a2=0.f;

    for (int m0 = 0; m0 < Dn; m0 += 32) {
        __syncthreads();
        #pragma unroll
        for (int i = tid; i < Sn * 8; i += 256) {
            int row = i >> 3, mm = (i & 7) << 2;
            *(float4*)&uh_sh[row][mm] =
                *(const float4*)(uh + ((size_t)(b*Sn + row)) * Dn + m0 + mm);
        }
        __syncthreads();

        #pragma unroll
        for (int mm = 0; mm < 32; mm += 4) {
            float4 wv = *(const float4*)&wq_sh[tloc][m0 + mm];
            float4 vv = *(const float4*)&v_sh[m0 + mm];
            float4 u0 = *(const float4*)&uh_sh[sbas     ][mm];
            float4 u1 = *(const float4*)&uh_sh[sbas + 32][mm];
            float4 u2 = *(const float4*)&uh_sh[sbas + 64][mm];
            a0 += tanh_fast(wv.x+u0.x)*vv.x; a0 += tanh_fast(wv.y+u0.y)*vv.y;
            a0 += tanh_fast(wv.z+u0.z)*vv.z; a0 += tanh_fast(wv.w+u0.w)*vv.w;
            a1 += tanh_fast(wv.x+u1.x)*vv.x; a1 += tanh_fast(wv.y+u1.y)*vv.y;
            a1 += tanh_fast(wv.z+u1.z)*vv.z; a1 += tanh_fast(wv.w+u1.w)*vv.w;
            a2 += tanh_fast(wv.x+u2.x)*vv.x; a2 += tanh_fast(wv.y+u2.y)*vv.y;
            a2 += tanh_fast(wv.z+u2.z)*vv.z; a2 += tanh_fast(wv.w+u2.w)*vv.w;
        }
    }

    const int L = lens[b];
    float vals[3] = {a0, a1, a2};
    float mx = -INFINITY;
    #pragma unroll
    for (int k = 0; k < 3; k++) {
        if (sbas + 32*k >= L) vals[k] = -INFINITY;
        mx = fmaxf(mx, vals[k]);
    }
    #pragma unroll
    for (int o = 16; o; o >>= 1) mx = fmaxf(mx, __shfl_xor_sync(0xFFFFFFFFu, mx, o));
    __syncthreads();
    if (lane == 0) rmax[w] = mx;
    __syncthreads();
    const float M = fmaxf(rmax[w], rmax[w ^ 1]);

    float sum = 0.f;
    #pragma unroll
    for (int k = 0; k < 3; k++) {
        float e = (vals[k] == -INFINITY) ? 0.f : __expf(vals[k] - M);
        vals[k] = e; sum += e;
    }
    #pragma unroll
    for (int o = 16; o; o >>= 1) sum += __shfl_xor_sync(0xFFFFFFFFu, sum, o);
    if (lane == 0) rsum[w] = sum;
    __syncthreads();
    const float inv = __fdividef(1.f, rsum[w] + rsum[w ^ 1]);

    const size_t rb = ((size_t)(b*Tn + t0 + tloc)) * Sn + sbas;
    #pragma unroll
    for (int k = 0; k < 3; k++) {
        float p = vals[k] * inv;
        P[rb + 32*k] = p;
        if (write_align) out_align[rb + 32*k] = p;
    }
}

// ----------------------------------------------------------------------------
// Stage 3: out[b,t,:] = P[b] @ Wm[b] + base (unchanged).
// ----------------------------------------------------------------------------
__global__ void __launch_bounds__(128) stage3_epilogue(
    const float* __restrict__ P, const float* __restrict__ Wm,
    const float* __restrict__ base, float* __restrict__ out)
{
    const int b  = blockIdx.z;
    const int m0 = blockIdx.y * 16;
    const int n0 = blockIdx.x * 64;
    const float* A  = P  + (size_t)b * Tn * Sn;
    const float* Bm = Wm + (size_t)b * Sn * Dn;

    __shared__ __align__(16) float As[16][20];
    __shared__ __align__(16) float Bs[16][68];

    const int tid = threadIdx.x;
    const int tm = tid >> 4;
    const int tn = tid & 15;

    float acc[2][4] = {};

    for (int k0 = 0; k0 < Sn; k0 += 16) {
        if (tid < 64) {
            int m = tid >> 2, k4 = (tid & 3) << 2;
            float4 a4 = *(const float4*)(A + (size_t)(m0 + m) * Sn + k0 + k4);
            As[k4+0][m] = a4.x; As[k4+1][m] = a4.y;
            As[k4+2][m] = a4.z; As[k4+3][m] = a4.w;
        }
        {
            int kk = tid >> 4, nn = (tid & 15) << 2;
            float4 b0 = *(const float4*)(Bm + (size_t)(k0 + kk)     * Dn + n0 + nn);
            float4 b1 = *(const float4*)(Bm + (size_t)(k0 + kk + 8) * Dn + n0 + nn);
            *(float4*)&Bs[kk][nn]     = b0;
            *(float4*)&Bs[kk + 8][nn] = b1;
        }
        __syncthreads();

        #pragma unroll
        for (int k = 0; k < 16; k++) {
            float a0 = As[k][tm*2], a1 = As[k][tm*2+1];
            float4 bv = *(const float4*)&Bs[k][tn*4];
            acc[0][0] += a0*bv.x; acc[0][1] += a0*bv.y; acc[0][2] += a0*bv.z; acc[0][3] += a0*bv.w;
            acc[1][0] += a1*bv.x; acc[1][1] += a1*bv.y; acc[1][2] += a1*bv.z; acc[1][3] += a1*bv.w;
        }
        __syncthreads();
    }

    #pragma unroll
    for (int i = 0; i < 2; i++) {
        const size_t r = (size_t)(b*Tn + m0 + tm*2 + i) * Dn + n0 + tn*4;
        float4 bb = *(const float4*)(base + r);
        float4 o;
        o.x = acc[i][0]+bb.x; o.y = acc[i][1]+bb.y;
        o.z = acc[i][2]+bb.z; o.w = acc[i][3]+bb.w;
        *(float4*)(out + r) = o;
    }
}

// ----------------------------------------------------------------------------
extern "C" void kernel_launch(void* const* d_in, const int* in_sizes, int n_in,
                              void* d_out, int out_size)
{
    const float* inputs = (const float*)d_in[0];
    const float* mems   = (const float*)d_in[1];
    const int*   lens   = (const int*)  d_in[2];
    const float* Wq     = (const float*)d_in[3];
    const float* Wc     = (const float*)d_in[4];
    const float* bc     = (const float*)d_in[5];
    const float* v      = (const float*)d_in[6];
    const float* Wout   = (const float*)d_in[7];
    const float* bout   = (const float*)d_in[8];
    float* out = (float*)d_out;

    float *wqb, *uhb, *wmb, *baseb, *pb;
    cudaGetSymbolAddress((void**)&wqb,   g_wq);
    cudaGetSymbolAddress((void**)&uhb,   g_uh);
    cudaGetSymbolAddress((void**)&wmb,   g_wm);
    cudaGetSymbolAddress((void**)&baseb, g_base);
    cudaGetSymbolAddress((void**)&pb,    g_p);

    const int attn_elems  = BT * Dn;
    const int align_elems = BT * Sn;
    const int write_align = (out_size >= attn_elems + align_elems) ? 1 : 0;
    float* out_align = out + attn_elems;

    cudaFuncSetAttribute(stage1_mma, cudaFuncAttributeMaxDynamicSharedMemorySize, S1_SMEM);

    // 1) wq, uh, Wm, base — pipelined + double-buffered mma.sync, 144 CTAs
    stage1_mma<<<dim3(Dn/128, 36), 256, S1_SMEM>>>(
        inputs, mems, Wq, Wc, bc, Wout, bout, wqb, uhb, wmb, baseb);

    // 2) score + masked softmax — 192 CTAs x 256 thr
    score_softmax<<<dim3(Tn/4, Bn), 256>>>(wqb, uhb, v, lens, pb, out_align, write_align);

    // 3) out = P @ Wm + base — 384 CTAs
    stage3_epilogue<<<dim3(Dn/64, Tn/16, Bn), 128>>>(pb, wmb, baseb, out);
}

// round 10
// speedup vs baseline: 2.1786x; 1.0432x over previous
#include <cuda_runtime.h>
#include <cuda_bf16.h>
#include <math.h>
#include <cstdint>

#define Bn 8
#define Tn 96
#define Sn 192
#define Dn 512
#define BT (Bn*Tn)   // 768
#define BS (Bn*Sn)   // 1536

// Scratch
__device__ float g_wq  [BT * Dn];
__device__ float g_uh  [BS * Dn];
__device__ float g_wm  [BS * Dn];
__device__ float g_base[BT * Dn];
__device__ float g_p   [BT * Sn];

__device__ __forceinline__ float tanh_fast(float x) {
    float y;
    asm("tanh.approx.f32 %0, %1;" : "=f"(y) : "f"(x));
    return y;
}

__device__ __forceinline__ uint32_t smem_u32(const void* p) {
    uint32_t a;
    asm("{ .reg .u64 t; cvta.to.shared.u64 t, %1; cvt.u32.u64 %0, t; }" : "=r"(a) : "l"(p));
    return a;
}
__device__ __forceinline__ void ldsm4(uint32_t* r, uint32_t addr) {
    asm volatile("ldmatrix.sync.aligned.m8n8.x4.shared.b16 {%0,%1,%2,%3}, [%4];"
        : "=r"(r[0]), "=r"(r[1]), "=r"(r[2]), "=r"(r[3]) : "r"(addr));
}
__device__ __forceinline__ void ldsm2(uint32_t* r, uint32_t addr) {
    asm volatile("ldmatrix.sync.aligned.m8n8.x2.shared.b16 {%0,%1}, [%2];"
        : "=r"(r[0]), "=r"(r[1]) : "r"(addr));
}
__device__ __forceinline__ void mma16816(float* c, const uint32_t* a, const uint32_t* b) {
    asm volatile(
        "mma.sync.aligned.m16n8k16.row.col.f32.bf16.bf16.f32 "
        "{%0,%1,%2,%3}, {%4,%5,%6,%7}, {%8,%9}, {%0,%1,%2,%3};"
        : "+f"(c[0]), "+f"(c[1]), "+f"(c[2]), "+f"(c[3])
        : "r"(a[0]), "r"(a[1]), "r"(a[2]), "r"(a[3]), "r"(b[0]), "r"(b[1]));
}

// ----------------------------------------------------------------------------
// Stage 1 via mma.sync bf16 (hi/lo split, 3 terms): C = A @ W^T (+bias), K=512.
// CTA tile 128x128, 512 thr = 16 warps (4 M x 4 N), warp tile 32x32.
// K-chunk 32, double-buffered smem, register-prefetched LDG.
// Grid (4, 36) = 144 CTAs.
// ----------------------------------------------------------------------------
#define PITCH 80
#define OAH 0
#define OAL 10240
#define OBH 20480
#define OBL 30720
#define BUFB 40960
#define S1_SMEM (2 * BUFB)   // 81920

__global__ void __launch_bounds__(512, 1) stage1_mma(
    const float* __restrict__ inputs, const float* __restrict__ mems,
    const float* __restrict__ Wq, const float* __restrict__ Wc,
    const float* __restrict__ bc, const float* __restrict__ Wout,
    const float* __restrict__ bout,
    float* __restrict__ wq_o, float* __restrict__ uh_o,
    float* __restrict__ wm_o, float* __restrict__ base_o)
{
    extern __shared__ __align__(16) unsigned char smem[];
    const uint32_t sb = smem_u32(smem);

    const int y = blockIdx.y;
    const float* A; const float* W; int ldw; const float* bias; float* C; int row0;
    if (y < 6)       { A = inputs; W = Wq;         ldw = 512;  bias = nullptr; C = wq_o;   row0 = y * 128; }
    else if (y < 18) { A = mems;   W = Wc;         ldw = 512;  bias = bc;      C = uh_o;   row0 = (y-6)*128; }
    else if (y < 30) { A = mems;   W = Wout;       ldw = 1024; bias = nullptr; C = wm_o;   row0 = (y-18)*128; }
    else             { A = inputs; W = Wout + 512; ldw = 1024; bias = bout;    C = base_o; row0 = (y-30)*128; }
    const int col0 = blockIdx.x * 128;

    const int tid  = threadIdx.x;
    const int wid  = tid >> 5;
    const int lane = tid & 31;
    const int wM   = wid >> 2;      // 0..3 -> rows wM*32..+31
    const int wN   = wid & 3;       // 0..3 -> cols wN*32..+31

    // convert-phase mapping: half a row (16 floats) per thread
    const int  crow  = (tid >> 1) & 127;       // row within tile
    const int  cisB  = tid >> 8;               // 0:A rows, 1:B rows
    const int  chalf = tid & 1;                // which 16-float half
    const float4* csrc4 = (const float4*)((cisB ? (W + (size_t)(col0 + crow) * ldw)
                                                : (A + (size_t)(row0 + crow) * Dn))
                                          + chalf * 16);
    const int cvtOff = (cisB ? OBH : OAH) + crow * PITCH + chalf * 32;  // hi; lo = +10240

    // ldmatrix per-warp offsets (relative to buffer base)
    const uint32_t aOffA = (uint32_t)((wM * 32 + (lane & 15)) * PITCH + ((lane >> 4) << 4));
    const uint32_t aOffB = (uint32_t)((wN * 32 + (lane & 7)) * PITCH + (((lane >> 3) & 1) << 4));

    float acc[2][4][4];
    #pragma unroll
    for (int i = 0; i < 2; i++)
        #pragma unroll
        for (int j = 0; j < 4; j++)
            #pragma unroll
            for (int q = 0; q < 4; q++) acc[i][j][q] = 0.f;

    float4 pre[4];
    #pragma unroll
    for (int j = 0; j < 4; j++) pre[j] = csrc4[j];

    // convert pre -> buffer 0
    {
        unsigned char* sHi = smem + cvtOff;
        unsigned char* sLo = sHi + 10240;
        uint32_t hi[8], lo[8];
        #pragma unroll
        for (int j = 0; j < 4; j++) {
            float4 f = pre[j];
            __nv_bfloat162 h01 = __float22bfloat162_rn(make_float2(f.x, f.y));
            __nv_bfloat162 h23 = __float22bfloat162_rn(make_float2(f.z, f.w));
            float2 g01 = __bfloat1622float2(h01);
            float2 g23 = __bfloat1622float2(h23);
            __nv_bfloat162 l01 = __float22bfloat162_rn(make_float2(f.x - g01.x, f.y - g01.y));
            __nv_bfloat162 l23 = __float22bfloat162_rn(make_float2(f.z - g23.x, f.w - g23.y));
            hi[2*j]   = *(uint32_t*)&h01; hi[2*j+1] = *(uint32_t*)&h23;
            lo[2*j]   = *(uint32_t*)&l01; lo[2*j+1] = *(uint32_t*)&l23;
        }
        *(uint4*)(sHi)      = make_uint4(hi[0], hi[1], hi[2], hi[3]);
        *(uint4*)(sHi + 16) = make_uint4(hi[4], hi[5], hi[6], hi[7]);
        *(uint4*)(sLo)      = make_uint4(lo[0], lo[1], lo[2], lo[3]);
        *(uint4*)(sLo + 16) = make_uint4(lo[4], lo[5], lo[6], lo[7]);
    }
    __syncthreads();

    for (int c = 0; c < 16; c++) {
        const int cur = c & 1;
        const uint32_t bufc = sb + cur * BUFB;

        // LDG for next chunk (arrives while MMA below runs)
        if (c < 15) {
            #pragma unroll
            for (int j = 0; j < 4; j++) pre[j] = csrc4[(c + 1) * 8 + j];
        }

        // ---- MMA on current buffer: 2 k16-steps x 3 terms ----
        #pragma unroll
        for (int ks = 0; ks < 2; ks++) {
            const uint32_t kb = (uint32_t)(ks * 32);
            uint32_t Ah[2][4], Bh[4][2];
            #pragma unroll
            for (int mi = 0; mi < 2; mi++)
                ldsm4(Ah[mi], bufc + OAH + aOffA + mi * (16 * PITCH) + kb);
            #pragma unroll
            for (int ni = 0; ni < 4; ni++)
                ldsm2(Bh[ni], bufc + OBH + aOffB + ni * (8 * PITCH) + kb);
            #pragma unroll
            for (int mi = 0; mi < 2; mi++)
                #pragma unroll
                for (int ni = 0; ni < 4; ni++)
                    mma16816(acc[mi][ni], Ah[mi], Bh[ni]);

            uint32_t Al[2][4];
            #pragma unroll
            for (int mi = 0; mi < 2; mi++)
                ldsm4(Al[mi], bufc + OAL + aOffA + mi * (16 * PITCH) + kb);
            #pragma unroll
            for (int mi = 0; mi < 2; mi++)
                #pragma unroll
                for (int ni = 0; ni < 4; ni++)
                    mma16816(acc[mi][ni], Al[mi], Bh[ni]);

            uint32_t Bl[4][2];
            #pragma unroll
            for (int ni = 0; ni < 4; ni++)
                ldsm2(Bl[ni], bufc + OBL + aOffB + ni * (8 * PITCH) + kb);
            #pragma unroll
            for (int mi = 0; mi < 2; mi++)
                #pragma unroll
                for (int ni = 0; ni < 4; ni++)
                    mma16816(acc[mi][ni], Ah[mi], Bl[ni]);
        }

        // ---- convert prefetched chunk into the other buffer ----
        if (c < 15) {
            unsigned char* sHi = smem + (cur ^ 1) * BUFB + cvtOff;
            unsigned char* sLo = sHi + 10240;
            uint32_t hi[8], lo[8];
            #pragma unroll
            for (int j = 0; j < 4; j++) {
                float4 f = pre[j];
                __nv_bfloat162 h01 = __float22bfloat162_rn(make_float2(f.x, f.y));
                __nv_bfloat162 h23 = __float22bfloat162_rn(make_float2(f.z, f.w));
                float2 g01 = __bfloat1622float2(h01);
                float2 g23 = __bfloat1622float2(h23);
                __nv_bfloat162 l01 = __float22bfloat162_rn(make_float2(f.x - g01.x, f.y - g01.y));
                __nv_bfloat162 l23 = __float22bfloat162_rn(make_float2(f.z - g23.x, f.w - g23.y));
                hi[2*j]   = *(uint32_t*)&h01; hi[2*j+1] = *(uint32_t*)&h23;
                lo[2*j]   = *(uint32_t*)&l01; lo[2*j+1] = *(uint32_t*)&l23;
            }
            *(uint4*)(sHi)      = make_uint4(hi[0], hi[1], hi[2], hi[3]);
            *(uint4*)(sHi + 16) = make_uint4(hi[4], hi[5], hi[6], hi[7]);
            *(uint4*)(sLo)      = make_uint4(lo[0], lo[1], lo[2], lo[3]);
            *(uint4*)(sLo + 16) = make_uint4(lo[4], lo[5], lo[6], lo[7]);
        }
        __syncthreads();
    }

    // ---- epilogue: acc regs -> gmem (+bias) ----
    const int erow = lane >> 2;
    const int ecol = (lane & 3) * 2;
    #pragma unroll
    for (int mi = 0; mi < 2; mi++) {
        const int r0 = row0 + wM * 32 + mi * 16 + erow;
        #pragma unroll
        for (int ni = 0; ni < 4; ni++) {
            const int cc = col0 + wN * 32 + ni * 8 + ecol;
            float b0 = 0.f, b1 = 0.f;
            if (bias) { b0 = bias[cc]; b1 = bias[cc + 1]; }
            float2 o0 = make_float2(acc[mi][ni][0] + b0, acc[mi][ni][1] + b1);
            float2 o1 = make_float2(acc[mi][ni][2] + b0, acc[mi][ni][3] + b1);
            *(float2*)(C + (size_t)r0 * Dn + cc)       = o0;
            *(float2*)(C + (size_t)(r0 + 8) * Dn + cc) = o1;
        }
    }
}

// ----------------------------------------------------------------------------
// Stage 2: fused score + masked softmax, 256 threads = 8 warps (unchanged).
// ----------------------------------------------------------------------------
__global__ void __launch_bounds__(256) score_softmax(
    const float* __restrict__ wq, const float* __restrict__ uh,
    const float* __restrict__ v, const int* __restrict__ lens,
    float* __restrict__ P, float* __restrict__ out_align, int write_align)
{
    const int t0 = blockIdx.x * 4;
    const int b  = blockIdx.y;
    const int tid = threadIdx.x, w = tid >> 5, lane = tid & 31;
    const int tloc = w >> 1;
    const int sh   = w & 1;
    const int sbas = sh * 96 + lane;

    __shared__ __align__(16) float wq_sh[4][Dn];
    __shared__ __align__(16) float v_sh[Dn];
    __shared__ __align__(16) float uh_sh[Sn][36];
    __shared__ float rmax[8], rsum[8];

    for (int i = tid; i < 4 * (Dn/4); i += 256) {
        int t = i >> 7, j = i & 127;
        ((float4*)wq_sh[t])[j] = ((const float4*)(wq + ((size_t)(b*Tn + t0 + t)) * Dn))[j];
    }
    for (int i = tid; i < Dn/4; i += 256)
        ((float4*)v_sh)[i] = ((const float4*)v)[i];

    float a0=0.f, a1=0.f, a2=0.f;

    for (int m0 = 0; m0 < Dn; m0 += 32) {
        __syncthreads();
        #pragma unroll
        for (int i = tid; i < Sn * 8; i += 256) {
            int row = i >> 3, mm = (i & 7) << 2;
            *(float4*)&uh_sh[row][mm] =
                *(const float4*)(uh + ((size_t)(b*Sn + row)) * Dn + m0 + mm);
        }
        __syncthreads();

        #pragma unroll
        for (int mm = 0; mm < 32; mm += 4) {
            float4 wv = *(const float4*)&wq_sh[tloc][m0 + mm];
            float4 vv = *(const float4*)&v_sh[m0 + mm];
            float4 u0 = *(const float4*)&uh_sh[sbas     ][mm];
            float4 u1 = *(const float4*)&uh_sh[sbas + 32][mm];
            float4 u2 = *(const float4*)&uh_sh[sbas + 64][mm];
            a0 += tanh_fast(wv.x+u0.x)*vv.x; a0 += tanh_fast(wv.y+u0.y)*vv.y;
            a0 += tanh_fast(wv.z+u0.z)*vv.z; a0 += tanh_fast(wv.w+u0.w)*vv.w;
            a1 += tanh_fast(wv.x+u1.x)*vv.x; a1 += tanh_fast(wv.y+u1.y)*vv.y;
            a1 += tanh_fast(wv.z+u1.z)*vv.z; a1 += tanh_fast(wv.w+u1.w)*vv.w;
            a2 += tanh_fast(wv.x+u2.x)*vv.x; a2 += tanh_fast(wv.y+u2.y)*vv.y;
            a2 += tanh_fast(wv.z+u2.z)*vv.z; a2 += tanh_fast(wv.w+u2.w)*vv.w;
        }
    }

    const int L = lens[b];
    float vals[3] = {a0, a1, a2};
    float mx = -INFINITY;
    #pragma unroll
    for (int k = 0; k < 3; k++) {
        if (sbas + 32*k >= L) vals[k] = -INFINITY;
        mx = fmaxf(mx, vals[k]);
    }
    #pragma unroll
    for (int o = 16; o; o >>= 1) mx = fmaxf(mx, __shfl_xor_sync(0xFFFFFFFFu, mx, o));
    __syncthreads();
    if (lane == 0) rmax[w] = mx;
    __syncthreads();
    const float M = fmaxf(rmax[w], rmax[w ^ 1]);

    float sum = 0.f;
    #pragma unroll
    for (int k = 0; k < 3; k++) {
        float e = (vals[k] == -INFINITY) ? 0.f : __expf(vals[k] - M);
        vals[k] = e; sum += e;
    }
    #pragma unroll
    for (int o = 16; o; o >>= 1) sum += __shfl_xor_sync(0xFFFFFFFFu, sum, o);
    if (lane == 0) rsum[w] = sum;
    __syncthreads();
    const float inv = __fdividef(1.f, rsum[w] + rsum[w ^ 1]);

    const size_t rb = ((size_t)(b*Tn + t0 + tloc)) * Sn + sbas;
    #pragma unroll
    for (int k = 0; k < 3; k++) {
        float p = vals[k] * inv;
        P[rb + 32*k] = p;
        if (write_align) out_align[rb + 32*k] = p;
    }
}

// ----------------------------------------------------------------------------
// Stage 3: out[b,t,:] = P[b] @ Wm[b] + base (unchanged).
// ----------------------------------------------------------------------------
__global__ void __launch_bounds__(128) stage3_epilogue(
    const float* __restrict__ P, const float* __restrict__ Wm,
    const float* __restrict__ base, float* __restrict__ out)
{
    const int b  = blockIdx.z;
    const int m0 = blockIdx.y * 16;
    const int n0 = blockIdx.x * 64;
    const float* A  = P  + (size_t)b * Tn * Sn;
    const float* Bm = Wm + (size_t)b * Sn * Dn;

    __shared__ __align__(16) float As[16][20];
    __shared__ __align__(16) float Bs[16][68];

    const int tid = threadIdx.x;
    const int tm = tid >> 4;
    const int tn = tid & 15;

    float acc[2][4] = {};

    for (int k0 = 0; k0 < Sn; k0 += 16) {
        if (tid < 64) {
            int m = tid >> 2, k4 = (tid & 3) << 2;
            float4 a4 = *(const float4*)(A + (size_t)(m0 + m) * Sn + k0 + k4);
            As[k4+0][m] = a4.x; As[k4+1][m] = a4.y;
            As[k4+2][m] = a4.z; As[k4+3][m] = a4.w;
        }
        {
            int kk = tid >> 4, nn = (tid & 15) << 2;
            float4 b0 = *(const float4*)(Bm + (size_t)(k0 + kk)     * Dn + n0 + nn);
            float4 b1 = *(const float4*)(Bm + (size_t)(k0 + kk + 8) * Dn + n0 + nn);
            *(float4*)&Bs[kk][nn]     = b0;
            *(float4*)&Bs[kk + 8][nn] = b1;
        }
        __syncthreads();

        #pragma unroll
        for (int k = 0; k < 16; k++) {
            float a0 = As[k][tm*2], a1 = As[k][tm*2+1];
            float4 bv = *(const float4*)&Bs[k][tn*4];
            acc[0][0] += a0*bv.x; acc[0][1] += a0*bv.y; acc[0][2] += a0*bv.z; acc[0][3] += a0*bv.w;
            acc[1][0] += a1*bv.x; acc[1][1] += a1*bv.y; acc[1][2] += a1*bv.z; acc[1][3] += a1*bv.w;
        }
        __syncthreads();
    }

    #pragma unroll
    for (int i = 0; i < 2; i++) {
        const size_t r = (size_t)(b*Tn + m0 + tm*2 + i) * Dn + n0 + tn*4;
        float4 bb = *(const float4*)(base + r);
        float4 o;
        o.x = acc[i][0]+bb.x; o.y = acc[i][1]+bb.y;
        o.z = acc[i][2]+bb.z; o.w = acc[i][3]+bb.w;
        *(float4*)(out + r) = o;
    }
}

// ----------------------------------------------------------------------------
extern "C" void kernel_launch(void* const* d_in, const int* in_sizes, int n_in,
                              void* d_out, int out_size)
{
    const float* inputs = (const float*)d_in[0];
    const float* mems   = (const float*)d_in[1];
    const int*   lens   = (const int*)  d_in[2];
    const float* Wq     = (const float*)d_in[3];
    const float* Wc     = (const float*)d_in[4];
    const float* bc     = (const float*)d_in[5];
    const float* v      = (const float*)d_in[6];
    const float* Wout   = (const float*)d_in[7];
    const float* bout   = (const float*)d_in[8];
    float* out = (float*)d_out;

    float *wqb, *uhb, *wmb, *baseb, *pb;
    cudaGetSymbolAddress((void**)&wqb,   g_wq);
    cudaGetSymbolAddress((void**)&uhb,   g_uh);
    cudaGetSymbolAddress((void**)&wmb,   g_wm);
    cudaGetSymbolAddress((void**)&baseb, g_base);
    cudaGetSymbolAddress((void**)&pb,    g_p);

    const int attn_elems  = BT * Dn;
    const int align_elems = BT * Sn;
    const int write_align = (out_size >= attn_elems + align_elems) ? 1 : 0;
    float* out_align = out + attn_elems;

    cudaFuncSetAttribute(stage1_mma, cudaFuncAttributeMaxDynamicSharedMemorySize, S1_SMEM);

    // 1) wq, uh, Wm, base — 512-thread pipelined mma.sync, 144 CTAs
    stage1_mma<<<dim3(Dn/128, 36), 512, S1_SMEM>>>(
        inputs, mems, Wq, Wc, bc, Wout, bout, wqb, uhb, wmb, baseb);

    // 2) score + masked softmax — 192 CTAs x 256 thr
    score_softmax<<<dim3(Tn/4, Bn), 256>>>(wqb, uhb, v, lens, pb, out_align, write_align);

    // 3) out = P @ Wm + base — 384 CTAs
    stage3_epilogue<<<dim3(Dn/64, Tn/16, Bn), 128>>>(pb, wmb, baseb, out);
}